// round 16
// baseline (speedup 1.0000x reference)
#include <cuda_runtime.h>
#include <cuda_bf16.h>

// Problem constants (fixed by the reference: B=4096, N=256, K=16)
#define NN    256
#define KK    16
#define PP    32640            // N*(N-1)/2
#define BB    4096
#define TPB   256              // threads per block
#define NG    2                // groups of 4 consecutive pairs per thread
#define TILE  (TPB * NG * 4)   // 2048 pairs per block tile
#define GX    16               // p-tiles: 16*2048 = 32768 >= 32640
#define ROWSB 64               // contiguous batch rows per block
#define GY    (BB / ROWSB)     // 64 -> grid 1024 blocks
#define CB    4                // rows per cleanup block
#define RU    2                // row unroll in main

// 4 shifted copies of x in GLOBAL memory (16 MB, L2-resident while hot):
//   g_xshift[r][b][k] = float4{ x[b][4k+r .. 4k+r+3] }
// This makes the arbitrary-offset 4-float gather a single ALIGNED LDG.128.
__device__ __align__(16) float4 g_xshift[4][BB][NN / 4];

// pstart(i) = number of pairs before row i = i*(N-1) - i*(i-1)/2
__host__ __device__ __forceinline__ int pstart(int i) {
    return i * (NN - 1) - (i * (i - 1)) / 2;
}

// invert triangular index p -> (i, j)
__device__ __forceinline__ void inv_tri(int pc, int& io, int& jo) {
    float disc = 2.0f * NN - 1.0f;       // 511
    int i = (int)floorf((disc - sqrtf(disc * disc - 8.0f * (float)pc)) * 0.5f);
    if (i < 0) i = 0;
    if (i > NN - 2) i = NN - 2;
    while (i < NN - 2 && pstart(i + 1) <= pc) i++;
    while (i > 0 && pstart(i) > pc) i--;
    io = i;
    jo = i + 1 + (pc - pstart(i));
}

// Guarded vector store: single @p STG.128, no BSSY/BSYNC branch envelope.
__device__ __forceinline__ void stg128_pred(float* ptr, float4 v, unsigned en) {
    asm volatile(
        "{\n\t"
        ".reg .pred sp;\n\t"
        "setp.ne.u32 sp, %0, 0;\n\t"
        "@sp st.global.v4.f32 [%1], {%2, %3, %4, %5};\n\t"
        "}"
        :: "r"(en), "l"(ptr), "f"(v.x), "f"(v.y), "f"(v.z), "f"(v.w)
        : "memory");
}

// ---------------------------------------------------------------------------
// Precompute kernel: build the 4 shifted copies of x. 20 MB of traffic, ~6us.
// One thread per (b, float4-slot).
// ---------------------------------------------------------------------------
__global__ void __launch_bounds__(TPB)
cross_utpm_shift(const float* __restrict__ x)
{
    int tid = blockIdx.x * TPB + threadIdx.x;    // 0 .. BB*64-1
    int b   = tid >> 6;
    int k   = tid & 63;

    size_t flat = (size_t)b * NN + 4 * k;
    float4 a = *reinterpret_cast<const float4*>(x + flat);
    size_t flatn = flat + 4;
    if (flatn > (size_t)BB * NN - 4) flatn = (size_t)BB * NN - 4;   // clamp (tail garbage unused)
    float4 bq = *reinterpret_cast<const float4*>(x + flatn);

    g_xshift[0][b][k] = a;
    g_xshift[1][b][k] = make_float4(a.y, a.z, a.w, bq.x);
    g_xshift[2][b][k] = make_float4(a.z, a.w, bq.x, bq.y);
    g_xshift[3][b][k] = make_float4(a.w, bq.x, bq.y, bq.z);
}

// ---------------------------------------------------------------------------
// Cleanup kernel: writes correct values for every group that straddles a row
// boundary. Main's guarded stores never touch those groups.
// ---------------------------------------------------------------------------
__global__ void __launch_bounds__(TPB)
cross_utpm_cleanup(const float* __restrict__ x,
                   const float* __restrict__ L,
                   float* __restrict__ out)
{
    __shared__ __align__(16) float xs[CB * NN];   // 4 KB

    const int t     = threadIdx.x;
    const int bbase = blockIdx.x * CB;

    {   // stage CB x-rows, coalesced: 256 float4 = one per thread
        const float4* src = reinterpret_cast<const float4*>(x + (size_t)bbase * NN);
        reinterpret_cast<float4*>(xs)[t] = src[t];
    }

    bool  flag = false;
    int   p0 = 0;
    int   ik[4], jk[4];
    float sp[4];

    if (t < NN - 2) {                 // i = t+1 in [1, 254]
        int i  = t + 1;
        int ps = pstart(i);
        flag = (ps & 3) != 0;
        if (flag) {
            p0 = ps & ~3;
#pragma unroll
            for (int k = 0; k < 4; k++) {
                inv_tri(p0 + k, ik[k], jk[k]);
                float s = 0.0f;
#pragma unroll
                for (int kk = 0; kk < KK; kk++)
                    s += L[ik[k] * KK + kk] * L[jk[k] * KK + kk];
                sp[k] = s;
            }
        }
    }
    __syncthreads();

    if (flag) {
#pragma unroll
        for (int r = 0; r < CB; r++) {
            const float* xr = xs + r * NN;
            float4 v;
            v.x = xr[ik[0]] * xr[jk[0]] * sp[0];
            v.y = xr[ik[1]] * xr[jk[1]] * sp[1];
            v.z = xr[ik[2]] * xr[jk[2]] * sp[2];
            v.w = xr[ik[3]] * xr[jk[3]] * sp[3];
            *reinterpret_cast<float4*>(out + (size_t)(bbase + r) * PP + p0) = v;
        }
    }
}

// ---------------------------------------------------------------------------
// Main kernel. NO shared memory, NO barriers, NO staging. Each warp runs
// free over its 64 rows. Per group per row:
//   LDG.32 xi (near-broadcast) + LDG.128 xj (aligned, from g_xshift copy
//   j0&3) + 8 FMUL + guarded @p STG.128.
// 2-row unroll gives 8 outstanding LDGs per warp for latency hiding.
// ---------------------------------------------------------------------------
__global__ void __launch_bounds__(TPB)
cross_utpm_main(const float* __restrict__ x,
                const float* __restrict__ L,
                float* __restrict__ out)
{
    const int t     = threadIdx.x;
    const int p0    = blockIdx.x * TILE;
    const int bbase = blockIdx.y * ROWSB;

    // ---- one-time per-thread setup (b-invariant) ----
    const float4* jptr[NG];    // &g_xshift[r][bbase][(j0-r)/4]; advance 64/row
    const float*  iptr[NG];    // &x[bbase*NN + i0];             advance 256/row
    int           poff[NG];    // output offset within the p-row
    unsigned      pen[NG];     // store-enable: valid AND single-row group
    float         sp[NG][4];

#pragma unroll
    for (int g = 0; g < NG; g++) {
        int pg = p0 + (g * TPB + t) * 4;
        bool valid = (pg < PP);
        int base = valid ? pg : 0;
        poff[g] = base;

        int i0, j0, i3, j3;
        inv_tri(base,     i0, j0);
        inv_tri(base + 3, i3, j3);
        pen[g] = (valid && (i0 == i3)) ? 1u : 0u;

        int r = j0 & 3;
        jptr[g] = &g_xshift[r][bbase][(j0 - r) >> 2];
        iptr[g] = x + (size_t)bbase * NN + i0;

#pragma unroll
        for (int k = 0; k < 4; k++) {
            int i, j;
            inv_tri(base + k, i, j);
            float s = 0.0f;
#pragma unroll
            for (int kk = 0; kk < KK; kk++)
                s += L[i * KK + kk] * L[j * KK + kk];
            sp[g][k] = s;
        }
    }

    // ---- free-running row loop, RU-row unroll for MLP ----
    float* orow = out + (size_t)bbase * PP;

    for (int s = 0; s < ROWSB; s += RU) {
        float  xiv[RU][NG];
        float4 xjv[RU][NG];

#pragma unroll
        for (int u = 0; u < RU; u++)
#pragma unroll
            for (int g = 0; g < NG; g++) {
                xiv[u][g] = __ldg(iptr[g] + u * NN);
                xjv[u][g] = __ldg(jptr[g] + u * (NN / 4));
            }

#pragma unroll
        for (int u = 0; u < RU; u++) {
#pragma unroll
            for (int g = 0; g < NG; g++) {
                float4 r4;
                r4.x = xiv[u][g] * xjv[u][g].x * sp[g][0];
                r4.y = xiv[u][g] * xjv[u][g].y * sp[g][1];
                r4.z = xiv[u][g] * xjv[u][g].z * sp[g][2];
                r4.w = xiv[u][g] * xjv[u][g].w * sp[g][3];
                stg128_pred(orow + (size_t)u * PP + poff[g], r4, pen[g]);
            }
        }

#pragma unroll
        for (int g = 0; g < NG; g++) {
            iptr[g] += RU * NN;
            jptr[g] += RU * (NN / 4);
        }
        orow += (size_t)RU * PP;
    }
}

extern "C" void kernel_launch(void* const* d_in, const int* in_sizes, int n_in,
                              void* d_out, int out_size)
{
    const float* x = (const float*)d_in[0];        // [4096, 256]
    const float* L = (const float*)d_in[1];        // [256, 16]
    float* out     = (float*)d_out;                // [4096, 32640]

    cross_utpm_shift<<<(BB * (NN / 4)) / TPB, TPB>>>(x);       // 1024 blocks, ~6us

    cross_utpm_cleanup<<<BB / CB, TPB>>>(x, L, out);           // 1024 blocks, ~10us

    dim3 gmain(GX, GY);                                        // (16, 64)
    cross_utpm_main<<<gmain, TPB>>>(x, L, out);
}

// round 17
// speedup vs baseline: 1.1822x; 1.1822x over previous
#include <cuda_runtime.h>
#include <cuda_bf16.h>
#include <cstdint>

// Problem constants (fixed by the reference: B=4096, N=256, K=16)
#define NN    256
#define KK    16
#define PP    32640            // N*(N-1)/2
#define BB    4096
#define TPB   256              // threads per block
#define NG    2                // groups of 4 consecutive pairs per thread
#define TILE  (TPB * NG * 4)   // 2048 pairs per block tile
#define GX    16               // p-tiles: 16*2048 = 32768 >= 32640
#define ROWSB 64               // contiguous batch rows per block
#define GY    (BB / ROWSB)     // 64 -> grid 1024 blocks
#define RST   4                // rows per super-stage
#define CS    256              // floats per shift copy

// pstart(i) = number of pairs before row i = i*(N-1) - i*(i-1)/2
__host__ __device__ __forceinline__ int pstart(int i) {
    return i * (NN - 1) - (i * (i - 1)) / 2;
}

// invert triangular index p -> (i, j)
__device__ __forceinline__ void inv_tri(int pc, int& io, int& jo) {
    float disc = 2.0f * NN - 1.0f;       // 511
    int i = (int)floorf((disc - sqrtf(disc * disc - 8.0f * (float)pc)) * 0.5f);
    if (i < 0) i = 0;
    if (i > NN - 2) i = NN - 2;
    while (i < NN - 2 && pstart(i + 1) <= pc) i++;
    while (i > 0 && pstart(i) > pc) i--;
    io = i;
    jo = i + 1 + (pc - pstart(i));
}

__device__ __forceinline__ uint32_t smem_u32(const void* p) {
    uint32_t a;
    asm("{ .reg .u64 tmp; cvta.to.shared.u64 tmp, %1; cvt.u32.u64 %0, tmp; }"
        : "=r"(a) : "l"(p));
    return a;
}

// ---------------------------------------------------------------------------
// Single kernel. Output is staged in SMEM and drained by TMA bulk stores —
// the SM never issues STG for the 535 MB output stream.
// Per super-stage (4 rows):
//   fill XS shift-copies -> compute (LDS + STS.128 into OB) -> sync ->
//   boundary fix-arm (few threads, amortized over 4 rows) -> fence -> sync ->
//   thread 0: 4x cp.async.bulk (8 KB each) + commit.
// Buffer reuse is guarded by cp.async.bulk.wait_group 0 at stage top.
// ---------------------------------------------------------------------------
__global__ void __launch_bounds__(TPB)
cross_utpm_kernel(const float* __restrict__ x,
                  const float* __restrict__ L,
                  float* __restrict__ out)
{
    __shared__ __align__(16) float XS[RST * 4 * CS];   // 16 KB: 4 rows x 4 shift copies
    __shared__ __align__(16) float OB[RST * TILE];     // 32 KB: 4 rows x 2048 outputs

    const int t     = threadIdx.x;
    const int p0    = blockIdx.x * TILE;
    const int bbase = blockIdx.y * ROWSB;

    // ---- one-time per-thread setup (b-invariant) ----
    int   offA[NG];      // offset (within a row's 4-copy region) of xj LDS.128
    int   offI[NG];      // offset of xi (copy 0)
    int   slot[NG];      // output slot within OB row buffer (always in [0,TILE))
    float sp[NG][4];

#pragma unroll
    for (int g = 0; g < NG; g++) {
        int pg = p0 + (g * TPB + t) * 4;
        bool valid = (pg < PP);
        int base = valid ? pg : 0;           // safe indices for invalid tail
        slot[g] = pg - p0;                   // invalid tail lands in non-copied region

        int i0, j0;
        inv_tri(base, i0, j0);
        offI[g] = i0;                        // copy 0 scalar
        int rA  = j0 & 3;
        offA[g] = rA * CS + (j0 - rA);       // 16B aligned within copy rA

#pragma unroll
        for (int k = 0; k < 4; k++) {
            int i, j;
            inv_tri(base + k, i, j);
            float s = 0.0f;
#pragma unroll
            for (int kk = 0; kk < KK; kk++)
                s += L[i * KK + kk] * L[j * KK + kk];
            sp[g][k] = s;
        }
    }

    // ---- boundary-fix setup: thread t owns candidate row-start i = t+1 ----
    // A group straddles rows iff some pstart(i) is not 4-aligned; the pairs
    // at p in [pstart(i), min(group_end, pstart(i+1))) belong to row i but
    // were computed with the group's first row. This thread rewrites them.
    bool  fixflag = false;
    int   fslot = 0, fcnt = 0, fxi = 0;
    float fsp[3];

    if (t < NN - 2) {
        int i  = t + 1;
        int ps = pstart(i);
        int g0 = ps & ~3;
        if ((ps & 3) != 0 && g0 >= p0 && g0 < p0 + TILE && g0 < PP) {
            fixflag = true;
            fslot = ps - p0;
            fcnt  = min(g0 + 4, pstart(i + 1)) - ps;   // 1..3 pairs
            fxi   = i;
#pragma unroll
            for (int k = 0; k < 3; k++) {
                int j = i + 1 + k;
                float s = 0.0f;
#pragma unroll
                for (int kk = 0; kk < KK; kk++)
                    s += L[i * KK + kk] * L[j * KK + kk];
                fsp[k] = s;
            }
        }
    }

    const int t6      = t & 63;      // float4 slot within a row (64 per row)
    const int rr_fill = t >> 6;      // which staged row this thread fills
    const size_t xmax = (size_t)BB * NN - 4;

    const uint32_t ob_base = smem_u32(OB);
    const unsigned szbytes = (unsigned)(min(TILE, PP - p0) * 4);   // 8192 or 7680

    for (int s = 0; s < ROWSB; s += RST) {
        int b0 = bbase + s;

        __syncthreads();                 // previous stage's XS readers done
        {
            // fill 4 shifted copies of RST rows via register shuffles
            size_t flat = (size_t)(b0 + rr_fill) * NN + 4 * t6;
            float4 a = *reinterpret_cast<const float4*>(x + flat);
            size_t flatn = flat + 4;
            if (flatn > xmax) flatn = xmax;
            float4 bq = *reinterpret_cast<const float4*>(x + flatn);

            float* Sr = XS + rr_fill * 4 * CS;
            reinterpret_cast<float4*>(Sr + 0 * CS)[t6] = a;
            reinterpret_cast<float4*>(Sr + 1 * CS)[t6] = make_float4(a.y, a.z, a.w, bq.x);
            reinterpret_cast<float4*>(Sr + 2 * CS)[t6] = make_float4(a.z, a.w, bq.x, bq.y);
            reinterpret_cast<float4*>(Sr + 3 * CS)[t6] = make_float4(a.w, bq.x, bq.y, bq.z);
        }
        if (t == 0)                      // OB free: previous stage's bulks done
            asm volatile("cp.async.bulk.wait_group 0;" ::: "memory");
        __syncthreads();                 // XS visible, OB reusable

        // ---- compute RST rows x NG groups into OB (STS.128, conflict-free) ----
#pragma unroll
        for (int rr = 0; rr < RST; rr++) {
            const float* Sr = XS + rr * 4 * CS;
            float* obr = OB + rr * TILE;
#pragma unroll
            for (int g = 0; g < NG; g++) {
                float  xi = Sr[offI[g]];                                     // LDS.32
                float4 xj = *reinterpret_cast<const float4*>(Sr + offA[g]);  // LDS.128
                float4 r4;
                r4.x = xi * xj.x * sp[g][0];
                r4.y = xi * xj.y * sp[g][1];
                r4.z = xi * xj.z * sp[g][2];
                r4.w = xi * xj.w * sp[g][3];
                *reinterpret_cast<float4*>(obr + slot[g]) = r4;              // STS.128
            }
        }
        __syncthreads();                 // garbage boundary values written

        // ---- boundary fix: few threads rewrite their row's wrong pairs ----
        if (fixflag) {
#pragma unroll
            for (int rr = 0; rr < RST; rr++) {
                const float* X0 = XS + rr * 4 * CS;    // copy 0 = unshifted row
                float xiv = X0[fxi];
                float* obr = OB + rr * TILE;
                for (int k = 0; k < fcnt; k++)
                    obr[fslot + k] = xiv * X0[fxi + 1 + k] * fsp[k];
            }
        }
        asm volatile("fence.proxy.async.shared::cta;" ::: "memory");
        __syncthreads();                 // fixes + fences complete

        // ---- TMA bulk store: 4 rows x 8 KB, one commit group ----
        if (t == 0) {
#pragma unroll
            for (int rr = 0; rr < RST; rr++) {
                const float* gptr = out + (size_t)(b0 + rr) * PP + p0;
                asm volatile(
                    "cp.async.bulk.global.shared::cta.bulk_group [%0], [%1], %2;"
                    :: "l"(gptr), "r"(ob_base + rr * TILE * 4), "r"(szbytes)
                    : "memory");
            }
            asm volatile("cp.async.bulk.commit_group;" ::: "memory");
        }
    }

    // drain outstanding bulk stores before block exit
    if (t == 0)
        asm volatile("cp.async.bulk.wait_group 0;" ::: "memory");
}

extern "C" void kernel_launch(void* const* d_in, const int* in_sizes, int n_in,
                              void* d_out, int out_size)
{
    const float* x = (const float*)d_in[0];        // [4096, 256]
    const float* L = (const float*)d_in[1];        // [256, 16]
    float* out     = (float*)d_out;                // [4096, 32640]

    dim3 grid(GX, GY);                             // (16, 64)
    cross_utpm_kernel<<<grid, TPB>>>(x, L, out);
}